// round 1
// baseline (speedup 1.0000x reference)
#include <cuda_runtime.h>

// Problem constants (fixed by the reference)
#define NF      128          // IN_FEATURES == OUT_FEATURES
#define NBATCH  2048
#define NTABLES (NF*NF)      // 16384

// Tiling
#define ROWS    64           // batch rows per CTA
#define OTILE   8            // outputs per CTA
#define XSTRIDE 68           // floats per feature row in smem (68*4=272B, 16B-aligned, padded)

typedef unsigned long long u64;

// Scratch (allocation-free rule: __device__ globals)
__device__ float4 g_cBC[NTABLES];   // (B,B,C,C) packed for f32x2
__device__ float2 g_cD[NTABLES];    // (D,D)
__device__ uchar2 g_mT[NTABLES];    // (m0,m1), transposed layout [i*NF + o]
__device__ float  g_Aout[NF];       // bias[o] + sum_i A

// ---------------------------------------------------------------------------
// Prepass: weight (TABLES,4) -> bilinear coefficients, transposed to [i][o],
// plus per-output constant Aout = bias + sum_i A.
// Grid: NF blocks (o), NF threads (i).
// ---------------------------------------------------------------------------
__global__ void prep_kernel(const float4* __restrict__ w,
                            const float*  __restrict__ bias,
                            const int*    __restrict__ mask) {
    int o = blockIdx.x;
    int i = threadIdx.x;
    int t = o * NF + i;                 // table id (coalesced read over i)
    float4 wv = w[t];
    float A = 0.25f * ( wv.x + wv.y + wv.z + wv.w);
    float B = 0.25f * (-wv.x + wv.y - wv.z + wv.w);
    float C = 0.25f * (-wv.x - wv.y + wv.z + wv.w);
    float D = 0.25f * ( wv.x - wv.y - wv.z + wv.w);
    int idx = i * NF + o;               // transposed (scattered write, one-time cost)
    g_cBC[idx] = make_float4(B, B, C, C);
    g_cD[idx]  = make_float2(D, D);
    g_mT[idx]  = make_uchar2((unsigned char)mask[2*t], (unsigned char)mask[2*t+1]);

    __shared__ float sA[NF];
    sA[i] = A;
    __syncthreads();
    #pragma unroll
    for (int s = 64; s > 0; s >>= 1) {
        if (i < s) sA[i] += sA[i + s];
        __syncthreads();
    }
    if (i == 0) g_Aout[o] = bias[o] + sA[0];
}

// Packed f32x2 math (Blackwell sm_100+)
#define FFMA2(d,a,b,c) asm("fma.rn.f32x2 %0, %1, %2, %3;" : "=l"(d) : "l"(a), "l"(b), "l"(c))
#define FMUL2(d,a,b)   asm("mul.rn.f32x2 %0, %1, %2;"     : "=l"(d) : "l"(a), "l"(b))

// ---------------------------------------------------------------------------
// Main kernel. CTA = (64 batch rows) x (8 outputs), loops all 128 tables/out.
// Thread = (o in tile, row-chunk of 4). x tile lives in smem transposed
// [feature][row] so one LDS.128 feeds 4 batch rows; accumulate in f32x2 pairs.
// Grid: (NBATCH/ROWS, NF/OTILE) = (32, 16); 128 threads.
// ---------------------------------------------------------------------------
__global__ __launch_bounds__(128) void main_kernel(const float* __restrict__ x,
                                                   float* __restrict__ out) {
    __shared__ __align__(16) float xs[NF * XSTRIDE];

    int tid = threadIdx.x;
    int b0  = blockIdx.x * ROWS;
    int o   = tid & (OTILE - 1);
    int rc  = tid >> 3;                      // 0..15 -> rows rc*4 .. rc*4+3
    int og  = blockIdx.y * OTILE + o;

    // Load x tile transposed: coalesced float4 gmem reads, scalar smem stores.
    for (int idx = tid; idx < ROWS * (NF / 4); idx += 128) {
        int r  = idx >> 5;                   // 32 float4 per row
        int f4 = (idx & 31) << 2;
        float4 v = *(const float4*)(x + (b0 + r) * NF + f4);
        xs[(f4 + 0) * XSTRIDE + r] = v.x;
        xs[(f4 + 1) * XSTRIDE + r] = v.y;
        xs[(f4 + 2) * XSTRIDE + r] = v.z;
        xs[(f4 + 3) * XSTRIDE + r] = v.w;
    }
    __syncthreads();

    const float*  xbase = xs + rc * 4;       // 16B-aligned (rc*16B)
    const float4* pBC = g_cBC + og;
    const float2* pD  = g_cD  + og;
    const uchar2* pM  = g_mT  + og;

    u64 a01 = 0ull, a23 = 0ull;              // f32x2 accumulators: rows (0,1),(2,3)

    #pragma unroll 4
    for (int i = 0; i < NF; i++) {
        uchar2 m = pM[i * NF];
        ulonglong2 bc = *(const ulonglong2*)(pBC + i * NF);  // (B,B) | (C,C)
        u64        dd = *(const u64*)      (pD  + i * NF);   // (D,D)
        // gather 4 rows of x[m0], x[m1] as two f32x2 each (one LDS.128 each)
        ulonglong2 x0 = *(const ulonglong2*)(xbase + (int)m.x * XSTRIDE);
        ulonglong2 x1 = *(const ulonglong2*)(xbase + (int)m.y * XSTRIDE);
        u64 p0, p1;
        FMUL2(p0, x0.x, x1.x);
        FMUL2(p1, x0.y, x1.y);
        FFMA2(a01, bc.x, x0.x, a01);
        FFMA2(a23, bc.x, x0.y, a23);
        FFMA2(a01, bc.y, x1.x, a01);
        FFMA2(a23, bc.y, x1.y, a23);
        FFMA2(a01, dd, p0, a01);
        FFMA2(a23, dd, p1, a23);
    }

    float aout = g_Aout[og];
    float2 v01 = *(float2*)&a01;
    float2 v23 = *(float2*)&a23;
    int r = b0 + rc * 4;
    out[(r + 0) * NF + og] = v01.x + aout;
    out[(r + 1) * NF + og] = v01.y + aout;
    out[(r + 2) * NF + og] = v23.x + aout;
    out[(r + 3) * NF + og] = v23.y + aout;
}

// ---------------------------------------------------------------------------
extern "C" void kernel_launch(void* const* d_in, const int* in_sizes, int n_in,
                              void* d_out, int out_size) {
    const float*  x    = (const float*) d_in[0];   // (2048,128) f32
    const float4* w    = (const float4*)d_in[1];   // (16384,4)  f32
    const float*  bias = (const float*) d_in[2];   // (128,)     f32
    const int*    mask = (const int*)   d_in[3];   // (32768,)   i32
    float* out = (float*)d_out;                    // (2048,128) f32

    prep_kernel<<<NF, NF>>>(w, bias, mask);
    dim3 grid(NBATCH / ROWS, NF / OTILE);          // (32,16) = 512 CTAs
    main_kernel<<<grid, 128>>>(x, out);
}

// round 2
// speedup vs baseline: 1.0354x; 1.0354x over previous
#include <cuda_runtime.h>

// Problem constants (fixed by the reference)
#define NF      128          // IN_FEATURES == OUT_FEATURES
#define NBATCH  2048
#define NTABLES (NF*NF)      // 16384

// Tiling
#define ROWS    64           // batch rows per CTA
#define OTILE   8            // outputs per CTA
#define XSTRIDE 68           // floats per feature row in smem (272B, 16B-aligned)
#define ZSPLIT  2            // i-loop split factor (threads per (o,rc))

typedef unsigned long long u64;

// Scratch (allocation-free rule: __device__ globals), layout [i*NF + o]
__device__ float4 g_c1[NTABLES];    // (B, B, C, C)
__device__ float4 g_c2[NTABLES];    // (D, D, byteoff(m0), byteoff(m1))
__device__ float  g_Aout[NF];       // bias[o] + sum_i A

// ---------------------------------------------------------------------------
// Prepass: weight (TABLES,4) -> bilinear coefficients, transposed to [i][o],
// with gather byte-offsets baked in. Grid: NF blocks (o), NF threads (i).
// ---------------------------------------------------------------------------
__global__ void prep_kernel(const float4* __restrict__ w,
                            const float*  __restrict__ bias,
                            const int*    __restrict__ mask) {
    int o = blockIdx.x;
    int i = threadIdx.x;
    int t = o * NF + i;                 // table id (coalesced over i)
    float4 wv = w[t];
    float A = 0.25f * ( wv.x + wv.y + wv.z + wv.w);
    float B = 0.25f * (-wv.x + wv.y - wv.z + wv.w);
    float C = 0.25f * (-wv.x - wv.y + wv.z + wv.w);
    float D = 0.25f * ( wv.x - wv.y - wv.z + wv.w);
    int m0 = mask[2 * t];
    int m1 = mask[2 * t + 1];
    int idx = i * NF + o;               // transposed (one-time scattered write)
    g_c1[idx] = make_float4(B, B, C, C);
    g_c2[idx] = make_float4(D, D,
                            __int_as_float(m0 * (XSTRIDE * 4)),
                            __int_as_float(m1 * (XSTRIDE * 4)));

    __shared__ float sA[NF];
    sA[i] = A;
    __syncthreads();
    #pragma unroll
    for (int s = 64; s > 0; s >>= 1) {
        if (i < s) sA[i] += sA[i + s];
        __syncthreads();
    }
    if (i == 0) g_Aout[o] = bias[o] + sA[0];
}

// Packed f32x2 math (sm_100+)
#define FFMA2(d,a,b,c) asm("fma.rn.f32x2 %0, %1, %2, %3;" : "=l"(d) : "l"(a), "l"(b), "l"(c))
#define FMUL2(d,a,b)   asm("mul.rn.f32x2 %0, %1, %2;"     : "=l"(d) : "l"(a), "l"(b))

// ---------------------------------------------------------------------------
// Main kernel. CTA = 64 batch rows x 8 outputs; 256 threads:
//   tid = o(8) + rc(16)*8 + z(2)*128.  Thread (o,rc,z) accumulates rows
//   rc*4..rc*4+3 of output og over tables i in [z*64, z*64+64), then z=0
//   combines z=1's partials from smem and stores.
// Grid: (NBATCH/ROWS, NF/OTILE) = (32, 16); 512 CTAs, 4096 warps.
// ---------------------------------------------------------------------------
__global__ __launch_bounds__(256) void main_kernel(const float* __restrict__ x,
                                                   float* __restrict__ out) {
    __shared__ __align__(16) float xs[NF * XSTRIDE];
    __shared__ __align__(16) float4 red[ROWS / 4 * OTILE];   // z=1 partials

    int tid = threadIdx.x;
    int b0  = blockIdx.x * ROWS;
    int o   = tid & (OTILE - 1);
    int rc  = (tid >> 3) & 15;               // 0..15 -> rows rc*4 .. rc*4+3
    int z   = tid >> 7;                      // 0,1
    int og  = blockIdx.y * OTILE + o;

    // Load x tile transposed: coalesced float4 gmem reads, scalar smem stores.
    for (int idx = tid; idx < ROWS * (NF / 4); idx += 256) {
        int r  = idx >> 5;                   // 32 float4 per row
        int f4 = (idx & 31) << 2;
        float4 v = *(const float4*)(x + (b0 + r) * NF + f4);
        xs[(f4 + 0) * XSTRIDE + r] = v.x;
        xs[(f4 + 1) * XSTRIDE + r] = v.y;
        xs[(f4 + 2) * XSTRIDE + r] = v.z;
        xs[(f4 + 3) * XSTRIDE + r] = v.w;
    }
    __syncthreads();

    const char* xb = (const char*)(xs + rc * 4);     // 16B-aligned base
    const ulonglong2* p1 = (const ulonglong2*)(g_c1 + (z * (NF / ZSPLIT)) * NF + og);
    const ulonglong2* p2 = (const ulonglong2*)(g_c2 + (z * (NF / ZSPLIT)) * NF + og);

    u64 a01 = 0ull, a23 = 0ull;              // f32x2 accumulators: rows (0,1),(2,3)

    #pragma unroll 4
    for (int i = 0; i < NF / ZSPLIT; i++) {
        ulonglong2 c1 = p1[i * NF];          // (B,B) | (C,C)
        ulonglong2 c2 = p2[i * NF];          // (D,D) | (off0,off1)
        uint2 offs = *(uint2*)&c2.y;
        ulonglong2 x0 = *(const ulonglong2*)(xb + offs.x);   // rows of x[m0]
        ulonglong2 x1 = *(const ulonglong2*)(xb + offs.y);   // rows of x[m1]
        u64 p0, p1v;
        FMUL2(p0,  x0.x, x1.x);
        FMUL2(p1v, x0.y, x1.y);
        FFMA2(a01, c1.x, x0.x, a01);
        FFMA2(a23, c1.x, x0.y, a23);
        FFMA2(a01, c1.y, x1.x, a01);
        FFMA2(a23, c1.y, x1.y, a23);
        FFMA2(a01, c2.x, p0,  a01);
        FFMA2(a23, c2.x, p1v, a23);
    }

    float2 v01 = *(float2*)&a01;
    float2 v23 = *(float2*)&a23;

    if (z == 1) {
        red[rc * OTILE + o] = make_float4(v01.x, v01.y, v23.x, v23.y);
    }
    __syncthreads();
    if (z == 0) {
        float4 p = red[rc * OTILE + o];
        float aout = g_Aout[og];
        int r = b0 + rc * 4;
        out[(r + 0) * NF + og] = v01.x + p.x + aout;
        out[(r + 1) * NF + og] = v01.y + p.y + aout;
        out[(r + 2) * NF + og] = v23.x + p.z + aout;
        out[(r + 3) * NF + og] = v23.y + p.w + aout;
    }
}

// ---------------------------------------------------------------------------
extern "C" void kernel_launch(void* const* d_in, const int* in_sizes, int n_in,
                              void* d_out, int out_size) {
    const float*  x    = (const float*) d_in[0];   // (2048,128) f32
    const float4* w    = (const float4*)d_in[1];   // (16384,4)  f32
    const float*  bias = (const float*) d_in[2];   // (128,)     f32
    const int*    mask = (const int*)   d_in[3];   // (32768,)   i32
    float* out = (float*)d_out;                    // (2048,128) f32

    prep_kernel<<<NF, NF>>>(w, bias, mask);
    dim3 grid(NBATCH / ROWS, NF / OTILE);          // (32,16) = 512 CTAs
    main_kernel<<<grid, 256>>>(x, out);
}

// round 3
// speedup vs baseline: 1.0470x; 1.0112x over previous
#include <cuda_runtime.h>

// Problem constants (fixed by the reference)
#define NF      128          // IN_FEATURES == OUT_FEATURES
#define NBATCH  2048
#define NTABLES (NF*NF)      // 16384

// Tiling
#define ROWS    64           // batch rows per CTA
#define OTILE   8            // outputs per CTA
#define XSTRIDE 68           // floats per feature row in smem (272B, 16B-aligned)
#define ZSPLIT  2            // i-loop split factor

typedef unsigned long long u64;

// Coefficients in CTA-blocked layout: [o>>3][i][o&7], each block 128*8 float4
__device__ float4 g_c1b[NTABLES];   // (B, B, C, C)
__device__ float4 g_c2b[NTABLES];   // (D, D, byteoff(m0), byteoff(m1))
__device__ float  g_Aout[NF];       // bias[o] + sum_i A

// ---------------------------------------------------------------------------
// Prepass: weight (TABLES,4) -> bilinear coefficients in CTA-blocked layout,
// with x-gather byte-offsets baked in. Grid: NF blocks (o), NF threads (i).
// ---------------------------------------------------------------------------
__global__ void prep_kernel(const float4* __restrict__ w,
                            const float*  __restrict__ bias,
                            const int*    __restrict__ mask) {
    int o = blockIdx.x;
    int i = threadIdx.x;
    int t = o * NF + i;                 // table id (coalesced over i)
    float4 wv = w[t];
    float A = 0.25f * ( wv.x + wv.y + wv.z + wv.w);
    float B = 0.25f * (-wv.x + wv.y - wv.z + wv.w);
    float C = 0.25f * (-wv.x - wv.y + wv.z + wv.w);
    float D = 0.25f * ( wv.x - wv.y - wv.z + wv.w);
    int m0 = mask[2 * t];
    int m1 = mask[2 * t + 1];
    int idx = (o >> 3) * (NF * OTILE) + i * OTILE + (o & 7);  // blocked
    g_c1b[idx] = make_float4(B, B, C, C);
    g_c2b[idx] = make_float4(D, D,
                             __int_as_float(m0 * (XSTRIDE * 4)),
                             __int_as_float(m1 * (XSTRIDE * 4)));

    __shared__ float sA[NF];
    sA[i] = A;
    __syncthreads();
    #pragma unroll
    for (int s = 64; s > 0; s >>= 1) {
        if (i < s) sA[i] += sA[i + s];
        __syncthreads();
    }
    if (i == 0) g_Aout[o] = bias[o] + sA[0];
}

// Packed f32x2 math (sm_100+)
#define FFMA2(d,a,b,c) asm("fma.rn.f32x2 %0, %1, %2, %3;" : "=l"(d) : "l"(a), "l"(b), "l"(c))
#define FMUL2(d,a,b)   asm("mul.rn.f32x2 %0, %1, %2;"     : "=l"(d) : "l"(a), "l"(b))

// Dynamic smem layout (bytes):
//   [0, 34816)              xs   : x tile transposed [feature][row], 128 x 68 f32
//   [34816, 51200)          sc1  : coeff slice (B,B,C,C), 128*8 float4
//   [51200, 67584)          sc2  : coeff slice (D,D,off0,off1), 128*8 float4
//   [67584, 69632)          red  : z=1 partials, 128 float4
#define SMEM_XS   0
#define SMEM_SC1  34816
#define SMEM_SC2  51200
#define SMEM_RED  67584
#define SMEM_TOT  69632

// ---------------------------------------------------------------------------
// Main kernel. CTA = 64 batch rows x 8 outputs; 256 threads:
//   tid = o(8) + rc(16)*8 + z(2)*128.  All LDG hoisted out of the inner loop:
//   x tile AND the CTA's 32KB coefficient slice are staged in smem.
// Grid: (NBATCH/ROWS, NF/OTILE) = (32, 16); 512 CTAs.
// ---------------------------------------------------------------------------
__global__ __launch_bounds__(256) void main_kernel(const float* __restrict__ x,
                                                   float* __restrict__ out) {
    extern __shared__ __align__(16) char sm[];
    float*  xs  = (float*) (sm + SMEM_XS);
    float4* sc1 = (float4*)(sm + SMEM_SC1);
    float4* sc2 = (float4*)(sm + SMEM_SC2);
    float4* red = (float4*)(sm + SMEM_RED);

    int tid = threadIdx.x;
    int b0  = blockIdx.x * ROWS;
    int o   = tid & (OTILE - 1);
    int rc  = (tid >> 3) & 15;               // 0..15 -> rows rc*4 .. rc*4+3
    int z   = tid >> 7;                      // 0,1
    int og  = blockIdx.y * OTILE + o;

    // Stage coefficient slice: straight 2 x 16KB coalesced copy.
    {
        const float4* src1 = g_c1b + blockIdx.y * (NF * OTILE);
        const float4* src2 = g_c2b + blockIdx.y * (NF * OTILE);
        #pragma unroll
        for (int k = 0; k < 4; k++) {
            sc1[tid + 256 * k] = src1[tid + 256 * k];
            sc2[tid + 256 * k] = src2[tid + 256 * k];
        }
    }

    // Stage x tile transposed: coalesced float4 gmem reads, scalar smem stores.
    for (int idx = tid; idx < ROWS * (NF / 4); idx += 256) {
        int r  = idx >> 5;                   // 32 float4 per row
        int f4 = (idx & 31) << 2;
        float4 v = *(const float4*)(x + (b0 + r) * NF + f4);
        xs[(f4 + 0) * XSTRIDE + r] = v.x;
        xs[(f4 + 1) * XSTRIDE + r] = v.y;
        xs[(f4 + 2) * XSTRIDE + r] = v.z;
        xs[(f4 + 3) * XSTRIDE + r] = v.w;
    }
    __syncthreads();

    const char* xb = (const char*)xs + rc * 16;          // 16B-aligned base
    const ulonglong2* p1 = (const ulonglong2*)(sc1 + (z * (NF / ZSPLIT)) * OTILE + o);
    const ulonglong2* p2 = (const ulonglong2*)(sc2 + (z * (NF / ZSPLIT)) * OTILE + o);

    u64 a01 = 0ull, a23 = 0ull;              // f32x2 accumulators: rows (0,1),(2,3)

    #pragma unroll 8
    for (int i = 0; i < NF / ZSPLIT; i++) {
        ulonglong2 c1 = p1[i * OTILE];       // (B,B) | (C,C)   LDS.128, bcast x4
        ulonglong2 c2 = p2[i * OTILE];       // (D,D) | (off0,off1)
        uint2 offs = *(uint2*)&c2.y;
        ulonglong2 x0 = *(const ulonglong2*)(xb + offs.x);   // 4 rows of x[m0]
        ulonglong2 x1 = *(const ulonglong2*)(xb + offs.y);   // 4 rows of x[m1]
        u64 p0, p1v;
        FMUL2(p0,  x0.x, x1.x);
        FMUL2(p1v, x0.y, x1.y);
        FFMA2(a01, c1.x, x0.x, a01);
        FFMA2(a23, c1.x, x0.y, a23);
        FFMA2(a01, c1.y, x1.x, a01);
        FFMA2(a23, c1.y, x1.y, a23);
        FFMA2(a01, c2.x, p0,  a01);
        FFMA2(a23, c2.x, p1v, a23);
    }

    float2 v01 = *(float2*)&a01;
    float2 v23 = *(float2*)&a23;

    if (z == 1) {
        red[rc * OTILE + o] = make_float4(v01.x, v01.y, v23.x, v23.y);
    }
    __syncthreads();
    if (z == 0) {
        float4 p = red[rc * OTILE + o];
        float aout = g_Aout[og];
        int r = b0 + rc * 4;
        out[(r + 0) * NF + og] = v01.x + p.x + aout;
        out[(r + 1) * NF + og] = v01.y + p.y + aout;
        out[(r + 2) * NF + og] = v23.x + p.z + aout;
        out[(r + 3) * NF + og] = v23.y + p.w + aout;
    }
}

// ---------------------------------------------------------------------------
extern "C" void kernel_launch(void* const* d_in, const int* in_sizes, int n_in,
                              void* d_out, int out_size) {
    const float*  x    = (const float*) d_in[0];   // (2048,128) f32
    const float4* w    = (const float4*)d_in[1];   // (16384,4)  f32
    const float*  bias = (const float*) d_in[2];   // (128,)     f32
    const int*    mask = (const int*)   d_in[3];   // (32768,)   i32
    float* out = (float*)d_out;                    // (2048,128) f32

    cudaFuncSetAttribute(main_kernel,
                         cudaFuncAttributeMaxDynamicSharedMemorySize, SMEM_TOT);

    prep_kernel<<<NF, NF>>>(w, bias, mask);
    dim3 grid(NBATCH / ROWS, NF / OTILE);          // (32,16) = 512 CTAs
    main_kernel<<<grid, 256, SMEM_TOT>>>(x, out);
}